// round 4
// baseline (speedup 1.0000x reference)
#include <cuda_runtime.h>
#include <math.h>

#define BB 64
#define HH 512
#define EE 512
#define SS 2048
#define VV 32000
#define NSPLIT 32
#define SPLIT_S (SS / NSPLIT)

#define FMA_F32X2(d, a, b, c) \
    asm("fma.rn.f32x2 %0, %1, %2, %3;" : "=l"(d) : "l"(a), "l"(b), "l"(c))
#define MUL_F32X2(d, a, b) \
    asm("mul.rn.f32x2 %0, %1, %2;" : "=l"(d) : "l"(a), "l"(b))
#define PACK_BCAST(d, f) \
    asm("mov.b64 %0, {%1, %1};" : "=l"(d) : "r"(__float_as_uint(f)))

typedef unsigned long long u64;

// ---------------- scratch ----------------
__device__ float g_x[BB * EE];
__device__ float g_gi[BB * 3 * HH];
__device__ float g_gh[BB * 3 * HH];
__device__ float g_A[BB * 2 * HH];          // [h_new | context]
__device__ float g_u[BB * HH];
__device__ float g_pctx[(size_t)NSPLIT * BB * HH];
__device__ float g_pml[NSPLIT * BB * 2];

// ---------------- K0: embed+ReLU (blocks 0..63) + zero scratch (64..127) ----
__global__ void k_prep(const int* __restrict__ idx, const float* __restrict__ emb) {
    if (blockIdx.x < 64) {
        int b = blockIdx.x, t = threadIdx.x;
        if (t < 128) {
            int row = idx[b];
            float4 v = ((const float4*)(emb + (size_t)row * EE))[t];
            v.x = fmaxf(v.x, 0.f); v.y = fmaxf(v.y, 0.f);
            v.z = fmaxf(v.z, 0.f); v.w = fmaxf(v.w, 0.f);
            ((float4*)(g_x + b * EE))[t] = v;
        }
    } else {
        int zi = (blockIdx.x - 64) * 256 + threadIdx.x;   // 0..16383
        float4 z = make_float4(0.f, 0.f, 0.f, 0.f);
        float4* pu  = (float4*)g_u;    // 8192 float4
        float4* pgi = (float4*)g_gi;   // 24576 float4
        float4* pgh = (float4*)g_gh;
        if (zi < 8192) pu[zi] = z;
        for (int i = zi; i < 24576; i += 16384) { pgi[i] = z; pgh[i] = z; }
    }
}

// ---------------- small GEMM tile: C[64, n0:n0+64] += A[:,k0:k0+64] * W ----
// BT=true : W[n][k] (row-major over n).  BT=false: W[k][n].
template<bool BT>
__device__ __forceinline__ void sgemm_tile(const float* __restrict__ A, int lda,
                                           const float* __restrict__ W, int ldw,
                                           float* __restrict__ C, int ldc,
                                           int n0, int k0) {
    __shared__ float As[64][68];   // [k][m]
    __shared__ float Bs[64][68];   // [k][n]
    const int tid = threadIdx.x;

#pragma unroll
    for (int r = 0; r < 4; r++) {
        int i = tid + r * 256;         // 0..1023
        int m = i >> 4, kq = (i & 15) * 4;
        float4 v = *(const float4*)(A + (size_t)m * lda + k0 + kq);
        As[kq + 0][m] = v.x; As[kq + 1][m] = v.y;
        As[kq + 2][m] = v.z; As[kq + 3][m] = v.w;
    }
#pragma unroll
    for (int r = 0; r < 4; r++) {
        int i = tid + r * 256;
        if (BT) {
            int n = i >> 4, kq = (i & 15) * 4;
            float4 v = *(const float4*)(W + (size_t)(n0 + n) * ldw + k0 + kq);
            Bs[kq + 0][n] = v.x; Bs[kq + 1][n] = v.y;
            Bs[kq + 2][n] = v.z; Bs[kq + 3][n] = v.w;
        } else {
            int k = i >> 4, nq = (i & 15) * 4;
            float4 v = *(const float4*)(W + (size_t)(k0 + k) * ldw + n0 + nq);
            *(float4*)&Bs[k][nq] = v;
        }
    }
    __syncthreads();

    const int mt = (tid >> 4) * 4;
    const int nt = (tid & 15) * 4;
    float acc[4][4];
#pragma unroll
    for (int i = 0; i < 4; i++)
#pragma unroll
        for (int j = 0; j < 4; j++) acc[i][j] = 0.f;

#pragma unroll
    for (int kk = 0; kk < 64; kk++) {
        float4 a = *(const float4*)&As[kk][mt];
        float4 b = *(const float4*)&Bs[kk][nt];
        float av[4] = {a.x, a.y, a.z, a.w};
        float bv[4] = {b.x, b.y, b.z, b.w};
#pragma unroll
        for (int i = 0; i < 4; i++)
#pragma unroll
            for (int j = 0; j < 4; j++) acc[i][j] += av[i] * bv[j];
    }
#pragma unroll
    for (int i = 0; i < 4; i++)
#pragma unroll
        for (int j = 0; j < 4; j++)
            atomicAdd(&C[(size_t)(mt + i) * ldc + n0 + nt + j], acc[i][j]);
}

// GRU gate GEMMs: grid (24 n-tiles, 8 k-tiles, 2 which)
__global__ void k_gru2(const float* __restrict__ h0,
                       const float* __restrict__ W_ih, const float* __restrict__ W_hh) {
    int n0 = blockIdx.x * 64, k0 = blockIdx.y * 64;
    if (blockIdx.z == 0)
        sgemm_tile<true>(g_x, EE, W_ih, EE, g_gi, 3 * HH, n0, k0);
    else
        sgemm_tile<true>(h0, HH, W_hh, HH, g_gh, 3 * HH, n0, k0);
}

// u = h @ W_attn : grid (8 n-tiles, 8 k-tiles)
__global__ void k_u2(const float* __restrict__ Wa) {
    sgemm_tile<false>(g_A, 1024, Wa, HH, g_u, HH, blockIdx.x * 64, blockIdx.y * 64);
}

// ---------------- GRU gate combine (bias folded in) ----------------
__global__ void k_gates(const float* __restrict__ h0,
                        const float* __restrict__ b_ih, const float* __restrict__ b_hh,
                        float* __restrict__ out_hidden) {
    int i = blockIdx.x * 256 + threadIdx.x;
    int b = i >> 9, h = i & 511;
    float gir = g_gi[b * 1536 + h]        + b_ih[h],        ghr = g_gh[b * 1536 + h]        + b_hh[h];
    float giz = g_gi[b * 1536 + 512 + h]  + b_ih[512 + h],  ghz = g_gh[b * 1536 + 512 + h]  + b_hh[512 + h];
    float gin = g_gi[b * 1536 + 1024 + h] + b_ih[1024 + h], ghn = g_gh[b * 1536 + 1024 + h] + b_hh[1024 + h];
    float r = 1.f / (1.f + __expf(-(gir + ghr)));
    float z = 1.f / (1.f + __expf(-(giz + ghz)));
    float n = tanhf(gin + r * ghn);
    float hv = (1.f - z) * n + z * h0[b * HH + h];
    g_A[b * 1024 + h] = hv;
    out_hidden[b * HH + h] = hv;
}

// ---------------- classifier: 64x128 tile, 256 thr, 4x8 micro, f32x2 ------
__global__ void k_cls(const float* __restrict__ W, const float* __restrict__ bias,
                      float* __restrict__ C) {
    __shared__ float As[2][16][68];
    __shared__ float Bs[2][16][132];
    const int tid = threadIdx.x;
    const int n0 = blockIdx.x * 128;
    const int mt = (tid >> 4) * 4;   // 0..60
    const int nt = (tid & 15) * 8;   // 0..120
    const float* A = g_A;            // 64 x 1024

    u64 acc2[4][4];
#pragma unroll
    for (int i = 0; i < 4; i++)
#pragma unroll
        for (int j = 0; j < 4; j++) acc2[i][j] = 0ull;

    float4 ra, rb[2];
    auto ldG = [&](int k0) {
        {
            int m = tid >> 2, kq = (tid & 3) * 4;
            ra = *(const float4*)(A + (size_t)m * 1024 + k0 + kq);
        }
#pragma unroll
        for (int r = 0; r < 2; r++) {
            int i = tid + r * 256;
            int n = i >> 2, kq = (i & 3) * 4;
            rb[r] = *(const float4*)(W + (size_t)(n0 + n) * 1024 + k0 + kq);
        }
    };
    auto stS = [&](int buf) {
        {
            int m = tid >> 2, kq = (tid & 3) * 4;
            As[buf][kq + 0][m] = ra.x; As[buf][kq + 1][m] = ra.y;
            As[buf][kq + 2][m] = ra.z; As[buf][kq + 3][m] = ra.w;
        }
#pragma unroll
        for (int r = 0; r < 2; r++) {
            int i = tid + r * 256;
            int n = i >> 2, kq = (i & 3) * 4;
            Bs[buf][kq + 0][n] = rb[r].x; Bs[buf][kq + 1][n] = rb[r].y;
            Bs[buf][kq + 2][n] = rb[r].z; Bs[buf][kq + 3][n] = rb[r].w;
        }
    };

    ldG(0);
    stS(0);
    __syncthreads();
#pragma unroll 1
    for (int t = 0; t < 64; t++) {
        const int cur = t & 1;
        if (t + 1 < 64) ldG((t + 1) * 16);
#pragma unroll
        for (int kk = 0; kk < 16; kk++) {
            float4 a = *(const float4*)&As[cur][kk][mt];
            const u64* bp = (const u64*)&Bs[cur][kk][nt];
            u64 pb0 = bp[0], pb1 = bp[1], pb2 = bp[2], pb3 = bp[3];
            float av[4] = {a.x, a.y, a.z, a.w};
#pragma unroll
            for (int i = 0; i < 4; i++) {
                u64 pa;
                PACK_BCAST(pa, av[i]);
                FMA_F32X2(acc2[i][0], pa, pb0, acc2[i][0]);
                FMA_F32X2(acc2[i][1], pa, pb1, acc2[i][1]);
                FMA_F32X2(acc2[i][2], pa, pb2, acc2[i][2]);
                FMA_F32X2(acc2[i][3], pa, pb3, acc2[i][3]);
            }
        }
        if (t + 1 < 64) stS(cur ^ 1);
        __syncthreads();
    }

    float4 b0 = *(const float4*)(bias + n0 + nt);
    float4 b1 = *(const float4*)(bias + n0 + nt + 4);
    float bi[8] = {b0.x, b0.y, b0.z, b0.w, b1.x, b1.y, b1.z, b1.w};
#pragma unroll
    for (int i = 0; i < 4; i++) {
        float o[8];
#pragma unroll
        for (int jp = 0; jp < 4; jp++) {
            float2 f = *reinterpret_cast<float2*>(&acc2[i][jp]);
            o[2 * jp] = f.x + bi[2 * jp];
            o[2 * jp + 1] = f.y + bi[2 * jp + 1];
        }
        size_t base = (size_t)(mt + i) * VV + n0 + nt;
        *(float4*)(C + base)     = make_float4(o[0], o[1], o[2], o[3]);
        *(float4*)(C + base + 4) = make_float4(o[4], o[5], o[6], o[7]);
    }
}

// ---------------- attention: warp-per-row, f32x2 math ----------------
__global__ void k_attn(const float* __restrict__ enc) {
    const int b = blockIdx.y;
    const int sp = blockIdx.x;
    const int t = threadIdx.x;
    const int wid = t >> 5, lane = t & 31;
    __shared__ float su[HH];
    __shared__ float sctx[8][HH];
    __shared__ float sml[8][2];

    su[t] = g_u[b * HH + t];
    su[t + 256] = g_u[b * HH + t + 256];
    __syncthreads();

    u64 u2[8];
#pragma unroll
    for (int j = 0; j < 4; j++) {
        float4 uu = ((const float4*)su)[lane + 32 * j];
        u2[2 * j]     = *(u64*)&uu.x;
        u2[2 * j + 1] = *(u64*)&uu.z;
    }

    float m = -INFINITY, l = 0.f;
    u64 acc2[8];
#pragma unroll
    for (int j = 0; j < 8; j++) acc2[j] = 0ull;

    const int s0 = sp * SPLIT_S;
    u64 v2[8];
    {
        const float4* row = (const float4*)(enc + ((size_t)(s0 + wid) * BB + b) * HH);
#pragma unroll
        for (int j = 0; j < 4; j++) {
            float4 v = row[lane + 32 * j];
            v2[2 * j] = *(u64*)&v.x;
            v2[2 * j + 1] = *(u64*)&v.z;
        }
    }

    for (int i = wid; i < SPLIT_S; i += 8) {
        u64 vn2[8];
        if (i + 8 < SPLIT_S) {
            const float4* rn = (const float4*)(enc + ((size_t)(s0 + i + 8) * BB + b) * HH);
#pragma unroll
            for (int j = 0; j < 4; j++) {
                float4 v = rn[lane + 32 * j];
                vn2[2 * j] = *(u64*)&v.x;
                vn2[2 * j + 1] = *(u64*)&v.z;
            }
        } else {
#pragma unroll
            for (int j = 0; j < 8; j++) vn2[j] = 0ull;
        }
        // dot via two independent f32x2 chains
        u64 p2a = 0ull, p2b = 0ull;
#pragma unroll
        for (int j = 0; j < 4; j++) {
            FMA_F32X2(p2a, v2[2 * j], u2[2 * j], p2a);
            FMA_F32X2(p2b, v2[2 * j + 1], u2[2 * j + 1], p2b);
        }
        float2 fa = *(float2*)&p2a, fb = *(float2*)&p2b;
        float p = (fa.x + fa.y) + (fb.x + fb.y);
#pragma unroll
        for (int o = 16; o; o >>= 1) p += __shfl_xor_sync(0xffffffffu, p, o);

        float nm = fmaxf(m, p);
        float sc = __expf(m - nm);
        float w = __expf(p - nm);
        l = l * sc + w;
        u64 sc2, w2;
        PACK_BCAST(sc2, sc);
        PACK_BCAST(w2, w);
#pragma unroll
        for (int j = 0; j < 8; j++) {
            u64 tmp;
            MUL_F32X2(tmp, w2, v2[j]);
            FMA_F32X2(acc2[j], acc2[j], sc2, tmp);
        }
        m = nm;
#pragma unroll
        for (int j = 0; j < 8; j++) v2[j] = vn2[j];
    }

#pragma unroll
    for (int j = 0; j < 4; j++) {
        float2 f0 = *(float2*)&acc2[2 * j];
        float2 f1 = *(float2*)&acc2[2 * j + 1];
        ((float4*)sctx[wid])[lane + 32 * j] = make_float4(f0.x, f0.y, f1.x, f1.y);
    }
    if (lane == 0) { sml[wid][0] = m; sml[wid][1] = l; }
    __syncthreads();

    float M = -INFINITY;
#pragma unroll
    for (int w = 0; w < 8; w++) M = fmaxf(M, sml[w][0]);
    float L = 0.f, c0 = 0.f, c1 = 0.f;
#pragma unroll
    for (int w = 0; w < 8; w++) {
        float e = __expf(sml[w][0] - M);
        L += e * sml[w][1];
        c0 += e * sctx[w][t];
        c1 += e * sctx[w][t + 256];
    }
    size_t base = ((size_t)sp * BB + b) * HH;
    g_pctx[base + t] = c0;
    g_pctx[base + t + 256] = c1;
    if (t == 0) {
        g_pml[(sp * BB + b) * 2] = M;
        g_pml[(sp * BB + b) * 2 + 1] = L;
    }
}

// ---------------- combine splits ----------------
__global__ void k_comb() {
    int b = blockIdx.x, t = threadIdx.x;
    __shared__ float sm[NSPLIT], sl[NSPLIT];
    if (t < NSPLIT) {
        sm[t] = g_pml[(t * BB + b) * 2];
        sl[t] = g_pml[(t * BB + b) * 2 + 1];
    }
    __syncthreads();
    float M = -INFINITY;
#pragma unroll
    for (int i = 0; i < NSPLIT; i++) M = fmaxf(M, sm[i]);
    float L = 0.f;
#pragma unroll
    for (int i = 0; i < NSPLIT; i++) L += sl[i] * __expf(sm[i] - M);
    float inv = 1.f / L;
    float o0 = 0.f, o1 = 0.f;
#pragma unroll
    for (int i = 0; i < NSPLIT; i++) {
        float w = __expf(sm[i] - M);
        size_t base = ((size_t)i * BB + b) * HH;
        o0 += w * g_pctx[base + t];
        o1 += w * g_pctx[base + t + 256];
    }
    g_A[b * 1024 + 512 + t] = o0 * inv;
    g_A[b * 1024 + 512 + t + 256] = o1 * inv;
}

// ---------------- fused log-softmax ----------------
__global__ void k_lsefix(float* __restrict__ out) {
    const int b = blockIdx.x, t = threadIdx.x;   // 1024 threads
    float4* row = (float4*)(out + (size_t)b * VV);
    __shared__ float red[32];
    __shared__ float sM, sL;
    const int lane = t & 31, wid = t >> 5;

    float mx = -INFINITY;
    for (int i = t; i < VV / 4; i += 1024) {
        float4 v = row[i];
        mx = fmaxf(mx, fmaxf(fmaxf(v.x, v.y), fmaxf(v.z, v.w)));
    }
#pragma unroll
    for (int o = 16; o; o >>= 1) mx = fmaxf(mx, __shfl_xor_sync(0xffffffffu, mx, o));
    if (lane == 0) red[wid] = mx;
    __syncthreads();
    if (t < 32) {
        float q = red[t];
#pragma unroll
        for (int o = 16; o; o >>= 1) q = fmaxf(q, __shfl_xor_sync(0xffffffffu, q, o));
        if (t == 0) sM = q;
    }
    __syncthreads();
    const float M = sM;

    float s = 0.f;
    for (int i = t; i < VV / 4; i += 1024) {
        float4 v = row[i];
        s += __expf(v.x - M) + __expf(v.y - M) + __expf(v.z - M) + __expf(v.w - M);
    }
#pragma unroll
    for (int o = 16; o; o >>= 1) s += __shfl_xor_sync(0xffffffffu, s, o);
    if (lane == 0) red[wid] = s;
    __syncthreads();
    if (t < 32) {
        float q = red[t];
#pragma unroll
        for (int o = 16; o; o >>= 1) q += __shfl_xor_sync(0xffffffffu, q, o);
        if (t == 0) sL = q;
    }
    __syncthreads();
    const float c = M + logf(sL);

    for (int i = t; i < VV / 4; i += 1024) {
        float4 v = row[i];
        v.x -= c; v.y -= c; v.z -= c; v.w -= c;
        row[i] = v;
    }
}

// ---------------- launch ----------------
extern "C" void kernel_launch(void* const* d_in, const int* in_sizes, int n_in,
                              void* d_out, int out_size) {
    const int*   dec_inputs = (const int*)d_in[0];
    const float* enc        = (const float*)d_in[1];
    const float* h0         = (const float*)d_in[2];
    const float* emb        = (const float*)d_in[3];
    const float* W_ih       = (const float*)d_in[4];
    const float* W_hh       = (const float*)d_in[5];
    const float* b_ih       = (const float*)d_in[6];
    const float* b_hh       = (const float*)d_in[7];
    const float* W_attn     = (const float*)d_in[8];
    const float* b_attn     = (const float*)d_in[9];   // cancels in softmax
    const float* W_cls      = (const float*)d_in[10];
    const float* b_cls      = (const float*)d_in[11];
    (void)b_attn; (void)in_sizes; (void)n_in; (void)out_size;

    float* out        = (float*)d_out;
    float* out_hidden = (float*)d_out + (size_t)BB * VV;

    k_prep<<<128, 256>>>(dec_inputs, emb);
    k_gru2<<<dim3(24, 8, 2), 256>>>(h0, W_ih, W_hh);
    k_gates<<<BB * HH / 256, 256>>>(h0, b_ih, b_hh, out_hidden);
    k_u2<<<dim3(8, 8), 256>>>(W_attn);
    k_attn<<<dim3(NSPLIT, BB), 256>>>(enc);
    k_comb<<<BB, 256>>>();
    k_cls<<<VV / 128, 256>>>(W_cls, b_cls, out);
    k_lsefix<<<BB, 1024>>>(out);
}